// round 1
// baseline (speedup 1.0000x reference)
#include <cuda_runtime.h>
#include <cstdint>

// ---------------------------------------------------------------------------
// SO2ConvolutionMoE:
//   ce = expert_coefficients[edge_batch]  (only 16 distinct systems)
//   -> premix weights per system, fold SO(2) real/imag recombination into the
//      B matrix ([[Wl, Wr], [-Wr, Wl]]), bucket edges by system, run 3 grouped
//      TF32 tensor-core GEMMs writing contiguous output rows.
// ---------------------------------------------------------------------------

#define NEDGES 12288
#define NSYS   16
#define NEXP   8
#define ROWF   2432          // 19*128 floats per edge (x and out share layout)
#define MAX_TILES 112        // sum ceil(cnt_s/128) <= 96 + 16

// Per-system premixed (and TF32-rounded) weights
__device__ float g_B0[(size_t)NSYS * 640 * 640];      // m0:   K=640,  N=640
__device__ float g_B1[(size_t)NSYS * 1024 * 1024];    // m1:   K=1024, N=1024
__device__ float g_B2[(size_t)NSYS * 768 * 768];      // m2:   K=768,  N=768
__device__ float g_bias0[NSYS * 640];
__device__ int   g_list[NSYS * NEDGES];
__device__ int   g_cnt[NSYS];
__device__ int   g_tsys[MAX_TILES];
__device__ int   g_tm0[MAX_TILES];
__device__ int   g_ntiles;

__device__ __forceinline__ float to_tf32(float x) {
    float r;
    asm("cvt.rna.tf32.f32 %0, %1;" : "=f"(r) : "f"(x));
    return r;
}

__device__ __forceinline__ void mma_tf32(float* d, const uint32_t* a, const uint32_t* b) {
    asm volatile(
        "mma.sync.aligned.m16n8k8.row.col.f32.tf32.tf32.f32 "
        "{%0,%1,%2,%3}, {%4,%5,%6,%7}, {%8,%9}, {%0,%1,%2,%3};\n"
        : "+f"(d[0]), "+f"(d[1]), "+f"(d[2]), "+f"(d[3])
        : "r"(a[0]), "r"(a[1]), "r"(a[2]), "r"(a[3]),
          "r"(b[0]), "r"(b[1]));
}

// ---------------------------------------------------------------------------
// Bucketing: edge -> system lists + tile plan
// ---------------------------------------------------------------------------
__global__ void reset_kernel() {
    if (threadIdx.x < NSYS) g_cnt[threadIdx.x] = 0;
}

__global__ void bucket_kernel(const int* __restrict__ eb) {
    int i = blockIdx.x * blockDim.x + threadIdx.x;
    if (i < NEDGES) {
        int s = eb[i];
        int p = atomicAdd(&g_cnt[s], 1);
        g_list[s * NEDGES + p] = i;
    }
}

__global__ void plan_kernel() {
    if (threadIdx.x == 0) {
        int nt = 0;
        for (int s = 0; s < NSYS; s++) {
            int c = g_cnt[s];
            for (int m0 = 0; m0 < c; m0 += 128) {
                g_tsys[nt] = s;
                g_tm0[nt]  = m0;
                nt++;
            }
        }
        g_ntiles = nt;
    }
}

// ---------------------------------------------------------------------------
// Weight mixing: per-system expert mix, SO(2) recombined layout, TF32-rounded.
//   MODE 0: B0[k][j]   = mix(W_m0[k][j])                        (640 x 640)
//   MODE 1/2 (so2), W is [Kin][Nw], B' is [2Kin][Nw], Nh = Nw/2:
//     k <  Kin:            B'[k][j]  =  W[k][j]
//     k >= Kin, j <  Nh:   B'[k][j]  = -W[k-Kin][Nh + j]
//     k >= Kin, j >= Nh:   B'[k][j]  =  W[k-Kin][j - Nh]
// ---------------------------------------------------------------------------
template <int MODE>
__global__ void mix_kernel(const float* __restrict__ W, const float* __restrict__ ec) {
    constexpr int Kin   = (MODE == 0) ? 640 : (MODE == 1) ? 512 : 384;
    constexpr int Nw    = (MODE == 0) ? 640 : (MODE == 1) ? 1024 : 768;
    constexpr int SO2   = (MODE == 0) ? 0 : 1;
    constexpr int TOTAL = (SO2 ? 2 * Kin : Kin) * Nw;

    float* Bd = (MODE == 0) ? g_B0 : (MODE == 1) ? g_B1 : g_B2;

    __shared__ float sec[NSYS * NEXP];
    if (threadIdx.x < NSYS * NEXP) sec[threadIdx.x] = ec[threadIdx.x];
    __syncthreads();

    int idx = blockIdx.x * blockDim.x + threadIdx.x;
    if (idx >= TOTAL) return;
    int k = idx / Nw;
    int j = idx - k * Nw;

    float sign = 1.f;
    size_t src;
    if (!SO2 || k < Kin) {
        src = (size_t)k * Nw + j;
    } else {
        int kk = k - Kin;
        int Nh = Nw >> 1;
        if (j < Nh) { src = (size_t)kk * Nw + Nh + j; sign = -1.f; }
        else        { src = (size_t)kk * Nw + (j - Nh); }
    }

    const size_t esz = (size_t)Kin * Nw;
    float w[NEXP];
#pragma unroll
    for (int e = 0; e < NEXP; e++) w[e] = W[e * esz + src];

#pragma unroll
    for (int s = 0; s < NSYS; s++) {
        float acc = 0.f;
#pragma unroll
        for (int e = 0; e < NEXP; e++) acc = fmaf(sec[s * NEXP + e], w[e], acc);
        Bd[(size_t)s * TOTAL + idx] = to_tf32(sign * acc);
    }
}

__global__ void biasmix_kernel(const float* __restrict__ b, const float* __restrict__ ec) {
    int j = blockIdx.x * blockDim.x + threadIdx.x;
    if (j >= 640) return;
    float w[NEXP];
#pragma unroll
    for (int e = 0; e < NEXP; e++) w[e] = b[e * 640 + j];
#pragma unroll
    for (int s = 0; s < NSYS; s++) {
        float acc = 0.f;
#pragma unroll
        for (int e = 0; e < NEXP; e++) acc = fmaf(ec[s * NEXP + e], w[e], acc);
        g_bias0[s * 640 + j] = acc;
    }
}

// ---------------------------------------------------------------------------
// Grouped TF32 GEMM: 128x128 CTA tile, K-tile 32, double-buffered.
// 8 warps (4M x 2N), each 32x64 via m16n8k8 (2 M-frags x 8 N-frags).
// A rows gathered through the per-system edge list; B per-system premixed.
// ---------------------------------------------------------------------------
#define KTILE 32
#define SA_STRIDE 36    // 128 rows x 36 (padded from 32): conflict-free A frag loads
#define SB_STRIDE 136   // 32 rows x 136 (padded from 128): conflict-free B frag loads
#define SMEM_FLOATS (2 * 128 * SA_STRIDE + 2 * KTILE * SB_STRIDE)
#define SMEM_BYTES ((SMEM_FLOATS + 128) * 4)

template <int SEG>
__global__ __launch_bounds__(256, 1) void gemm_kernel(
    const float* __restrict__ X, float* __restrict__ out) {
    constexpr int K    = (SEG == 0) ? 640 : (SEG == 1) ? 1024 : 768;
    constexpr int N    = K;
    constexpr int XOFF = (SEG == 0) ? 0 : (SEG == 1) ? 640 : 1664;
    constexpr int OOFF = XOFF;
    constexpr int KT   = K / KTILE;

    int ti = blockIdx.y;
    if (ti >= g_ntiles) return;
    const int sys = g_tsys[ti];
    const int m0  = g_tm0[ti];
    const int cnt = g_cnt[sys];
    const int n0  = blockIdx.x * 128;

    const float* Bw = (SEG == 0) ? g_B0 : (SEG == 1) ? g_B1 : g_B2;
    const float* Bsys = Bw + (size_t)sys * K * N;

    extern __shared__ float sm[];
    float* sA = sm;                             // [2][128][SA_STRIDE]
    float* sB = sm + 2 * 128 * SA_STRIDE;       // [2][32][SB_STRIDE]
    int*   sE = (int*)(sm + SMEM_FLOATS);       // [128] edge ids

    const int tid = threadIdx.x;

    if (tid < 128) {
        int idx = m0 + tid;
        sE[tid] = (idx < cnt) ? g_list[sys * NEDGES + idx] : -1;
    }
    __syncthreads();

    // --- A loader: 2 threads per row, 16 floats each (4 x float4) ---
    const int ar = tid >> 1, ah = tid & 1;
    const int aedge = sE[ar];
    const float* agp = (aedge >= 0) ? (X + (size_t)aedge * ROWF + XOFF + ah * 16) : nullptr;
    float* asd = sA + ar * SA_STRIDE + ah * 16;

    float4 areg[4];
    auto ldgA = [&](int kt) {
        if (aedge >= 0) {
            const float4* p = (const float4*)(agp + kt * KTILE);
            areg[0] = p[0]; areg[1] = p[1]; areg[2] = p[2]; areg[3] = p[3];
        } else {
            areg[0] = areg[1] = areg[2] = areg[3] = make_float4(0.f, 0.f, 0.f, 0.f);
        }
    };
    auto stsA = [&](int buf) {
        float* d = asd + buf * 128 * SA_STRIDE;
#pragma unroll
        for (int w = 0; w < 4; w++) {
            float4 v = areg[w];
            v.x = to_tf32(v.x); v.y = to_tf32(v.y);
            v.z = to_tf32(v.z); v.w = to_tf32(v.w);
            *(float4*)(d + w * 4) = v;
        }
    };
    auto cpB = [&](int kt, int buf) {
#pragma unroll
        for (int i = 0; i < 4; i++) {
            int chunk = tid + i * 256;
            int k = chunk >> 5, c = chunk & 31;
            const float* src = Bsys + (size_t)(kt * KTILE + k) * N + n0 + c * 4;
            float* dst = sB + buf * KTILE * SB_STRIDE + k * SB_STRIDE + c * 4;
            uint32_t sa = (uint32_t)__cvta_generic_to_shared(dst);
            asm volatile("cp.async.cg.shared.global [%0], [%1], 16;\n" :: "r"(sa), "l"(src));
        }
        asm volatile("cp.async.commit_group;\n" ::);
    };

    const int lane = tid & 31, warp = tid >> 5;
    const int wm = warp & 3, wn = warp >> 2;     // 4 M-warps x 2 N-warps
    const int gid = lane >> 2, tig = lane & 3;

    float acc[2][8][4];
#pragma unroll
    for (int a = 0; a < 2; a++)
#pragma unroll
        for (int b = 0; b < 8; b++)
#pragma unroll
            for (int c = 0; c < 4; c++) acc[a][b][c] = 0.f;

    // prologue
    cpB(0, 0);
    ldgA(0);
    stsA(0);
    asm volatile("cp.async.wait_group 0;\n" ::);
    __syncthreads();

    for (int kt = 0; kt < KT; kt++) {
        const int cur = kt & 1;
        if (kt + 1 < KT) { cpB(kt + 1, cur ^ 1); ldgA(kt + 1); }

        const float* cA = sA + cur * 128 * SA_STRIDE;
        const float* cB = sB + cur * KTILE * SB_STRIDE;
#pragma unroll
        for (int ks = 0; ks < 4; ks++) {
            const int k0 = ks * 8;
            uint32_t af[2][4], bf[8][2];
#pragma unroll
            for (int mt = 0; mt < 2; mt++) {
                int r = wm * 32 + mt * 16 + gid;
                af[mt][0] = __float_as_uint(cA[r * SA_STRIDE + k0 + tig]);
                af[mt][1] = __float_as_uint(cA[(r + 8) * SA_STRIDE + k0 + tig]);
                af[mt][2] = __float_as_uint(cA[r * SA_STRIDE + k0 + tig + 4]);
                af[mt][3] = __float_as_uint(cA[(r + 8) * SA_STRIDE + k0 + tig + 4]);
            }
#pragma unroll
            for (int nt = 0; nt < 8; nt++) {
                int c = wn * 64 + nt * 8 + gid;
                bf[nt][0] = __float_as_uint(cB[(k0 + tig) * SB_STRIDE + c]);
                bf[nt][1] = __float_as_uint(cB[(k0 + tig + 4) * SB_STRIDE + c]);
            }
#pragma unroll
            for (int mt = 0; mt < 2; mt++)
#pragma unroll
                for (int nt = 0; nt < 8; nt++)
                    mma_tf32(acc[mt][nt], af[mt], bf[nt]);
        }
        if (kt + 1 < KT) {
            stsA(cur ^ 1);
            asm volatile("cp.async.wait_group 0;\n" ::);
        }
        __syncthreads();
    }

    // epilogue: scatter rows back by edge id; contiguous 2-float stores
#pragma unroll
    for (int mt = 0; mt < 2; mt++) {
        int r0 = wm * 32 + mt * 16 + gid;
        int e0 = sE[r0], e1 = sE[r0 + 8];
#pragma unroll
        for (int nt = 0; nt < 8; nt++) {
            int col = n0 + wn * 64 + nt * 8 + tig * 2;
            float b0 = 0.f, b1 = 0.f;
            if (SEG == 0) {
                b0 = g_bias0[sys * 640 + col];
                b1 = g_bias0[sys * 640 + col + 1];
            }
            if (e0 >= 0) {
                float2 v;
                v.x = acc[mt][nt][0] + b0;
                v.y = acc[mt][nt][1] + b1;
                *(float2*)(out + (size_t)e0 * ROWF + OOFF + col) = v;
            }
            if (e1 >= 0) {
                float2 v;
                v.x = acc[mt][nt][2] + b0;
                v.y = acc[mt][nt][3] + b1;
                *(float2*)(out + (size_t)e1 * ROWF + OOFF + col) = v;
            }
        }
    }
}

// ---------------------------------------------------------------------------
extern "C" void kernel_launch(void* const* d_in, const int* in_sizes, int n_in,
                              void* d_out, int out_size) {
    const float* x   = (const float*)d_in[0];
    // d_in[1] = x_edge (unused by the reference computation)
    const float* ec  = (const float*)d_in[2];
    const int*   eb  = (const int*)d_in[3];
    const float* Wm0 = (const float*)d_in[4];
    const float* bm0 = (const float*)d_in[5];
    const float* Wm1 = (const float*)d_in[6];
    const float* Wm2 = (const float*)d_in[7];
    float* out = (float*)d_out;

    cudaFuncSetAttribute(gemm_kernel<0>, cudaFuncAttributeMaxDynamicSharedMemorySize, SMEM_BYTES);
    cudaFuncSetAttribute(gemm_kernel<1>, cudaFuncAttributeMaxDynamicSharedMemorySize, SMEM_BYTES);
    cudaFuncSetAttribute(gemm_kernel<2>, cudaFuncAttributeMaxDynamicSharedMemorySize, SMEM_BYTES);

    // bucketing + tile plan
    reset_kernel<<<1, 32>>>();
    bucket_kernel<<<(NEDGES + 255) / 256, 256>>>(eb);
    plan_kernel<<<1, 32>>>();

    // per-system weight mixing (TF32-rounded, SO(2)-recombined layout)
    mix_kernel<0><<<(640 * 640 + 255) / 256, 256>>>(Wm0, ec);
    mix_kernel<1><<<(1024 * 1024 + 255) / 256, 256>>>(Wm1, ec);
    mix_kernel<2><<<(768 * 768 + 255) / 256, 256>>>(Wm2, ec);
    biasmix_kernel<<<3, 256>>>(bm0, ec);

    // grouped GEMMs
    gemm_kernel<0><<<dim3(640 / 128, MAX_TILES), 256, SMEM_BYTES>>>(x, out);
    gemm_kernel<1><<<dim3(1024 / 128, MAX_TILES), 256, SMEM_BYTES>>>(x, out);
    gemm_kernel<2><<<dim3(768 / 128, MAX_TILES), 256, SMEM_BYTES>>>(x, out);
}

// round 3
// speedup vs baseline: 1.7751x; 1.7751x over previous
#include <cuda_runtime.h>
#include <cuda_fp16.h>
#include <cstdint>

// ---------------------------------------------------------------------------
// SO2ConvolutionMoE, FP16 tensor-core version:
//   - premix per-system expert weights (fp32 accum -> fp16), SO(2) recombine
//     folded into B' = [[Wl, Wr], [-Wr, Wl]]
//   - pre-convert x to fp16 once
//   - bucket edges by system, 3 grouped fp16 GEMMs (m16n8k16, ldmatrix,
//     cp.async 3-stage pipeline), fp32 accum + bias epilogue
// ---------------------------------------------------------------------------

#define NEDGES 12288
#define NSYS   16
#define NEXP   8
#define ROWF   2432          // 19*128 elems per edge row (x and out)
#define MAX_TILES 112

// per-system premixed fp16 weights
__device__ __half g_B0[(size_t)NSYS * 640 * 640];
__device__ __half g_B1[(size_t)NSYS * 1024 * 1024];
__device__ __half g_B2[(size_t)NSYS * 768 * 768];
__device__ float  g_bias0[NSYS * 640];
__device__ __half g_xh[(size_t)NEDGES * ROWF];      // fp16 copy of x
__device__ int    g_list[NSYS * NEDGES];
__device__ int    g_cnt[NSYS];
__device__ int    g_tsys[MAX_TILES];
__device__ int    g_tm0[MAX_TILES];
__device__ int    g_ntiles;

__device__ __forceinline__ uint32_t h2_as_u32(__half2 h) {
    return *reinterpret_cast<const uint32_t*>(&h);
}

// ---------------------------------------------------------------------------
__global__ void reset_kernel() {
    if (threadIdx.x < NSYS) g_cnt[threadIdx.x] = 0;
}

__global__ void bucket_kernel(const int* __restrict__ eb) {
    int i = blockIdx.x * blockDim.x + threadIdx.x;
    if (i < NEDGES) {
        int s = eb[i];
        int p = atomicAdd(&g_cnt[s], 1);
        g_list[s * NEDGES + p] = i;
    }
}

__global__ void plan_kernel() {
    if (threadIdx.x == 0) {
        int nt = 0;
        for (int s = 0; s < NSYS; s++) {
            int c = g_cnt[s];
            for (int m0 = 0; m0 < c; m0 += 128) {
                g_tsys[nt] = s;
                g_tm0[nt]  = m0;
                nt++;
            }
        }
        g_ntiles = nt;
    }
}

// x (fp32) -> g_xh (fp16), vectorized
__global__ void cvt_kernel(const float* __restrict__ x) {
    const int total4 = NEDGES * ROWF / 4;
    int i = blockIdx.x * blockDim.x + threadIdx.x;
    if (i >= total4) return;
    float4 v = ((const float4*)x)[i];
    uint2 u;
    u.x = h2_as_u32(__floats2half2_rn(v.x, v.y));
    u.y = h2_as_u32(__floats2half2_rn(v.z, v.w));
    *reinterpret_cast<uint2*>(g_xh + (size_t)i * 4) = u;
}

// ---------------------------------------------------------------------------
// Weight mixing (vectorized by 4 cols, fp16 output)
// ---------------------------------------------------------------------------
template <int MODE>
__global__ void mix_kernel(const float* __restrict__ W, const float* __restrict__ ec) {
    constexpr int Kin   = (MODE == 0) ? 640 : (MODE == 1) ? 512 : 384;
    constexpr int Nw    = (MODE == 0) ? 640 : (MODE == 1) ? 1024 : 768;
    constexpr int SO2   = (MODE == 0) ? 0 : 1;
    constexpr int KTOT  = SO2 ? 2 * Kin : Kin;
    constexpr int TOTAL = KTOT * Nw;
    constexpr int N4    = Nw / 4;

    __half* Bd = (MODE == 0) ? g_B0 : (MODE == 1) ? g_B1 : g_B2;

    __shared__ float sec[NSYS * NEXP];
    if (threadIdx.x < NSYS * NEXP) sec[threadIdx.x] = ec[threadIdx.x];
    __syncthreads();

    int idx4 = blockIdx.x * blockDim.x + threadIdx.x;
    if (idx4 >= TOTAL / 4) return;
    int k  = idx4 / N4;
    int jj = idx4 - k * N4;

    float sign = 1.f;
    size_t src4;
    if (!SO2 || k < Kin) {
        src4 = (size_t)k * N4 + jj;
    } else {
        int kk = k - Kin;
        int Nh4 = N4 >> 1;
        if (jj < Nh4) { src4 = (size_t)kk * N4 + Nh4 + jj; sign = -1.f; }
        else          { src4 = (size_t)kk * N4 + (jj - Nh4); }
    }

    const size_t esz4 = (size_t)Kin * N4;
    float4 w[NEXP];
#pragma unroll
    for (int e = 0; e < NEXP; e++) w[e] = ((const float4*)W)[e * esz4 + src4];

#pragma unroll
    for (int s = 0; s < NSYS; s++) {
        float4 a = make_float4(0.f, 0.f, 0.f, 0.f);
#pragma unroll
        for (int e = 0; e < NEXP; e++) {
            float c = sec[s * NEXP + e];
            a.x = fmaf(c, w[e].x, a.x); a.y = fmaf(c, w[e].y, a.y);
            a.z = fmaf(c, w[e].z, a.z); a.w = fmaf(c, w[e].w, a.w);
        }
        uint2 u;
        u.x = h2_as_u32(__floats2half2_rn(sign * a.x, sign * a.y));
        u.y = h2_as_u32(__floats2half2_rn(sign * a.z, sign * a.w));
        *reinterpret_cast<uint2*>(Bd + (size_t)s * TOTAL + (size_t)idx4 * 4) = u;
    }
}

__global__ void biasmix_kernel(const float* __restrict__ b, const float* __restrict__ ec) {
    int j = blockIdx.x * blockDim.x + threadIdx.x;
    if (j >= 640) return;
    float w[NEXP];
#pragma unroll
    for (int e = 0; e < NEXP; e++) w[e] = b[e * 640 + j];
#pragma unroll
    for (int s = 0; s < NSYS; s++) {
        float acc = 0.f;
#pragma unroll
        for (int e = 0; e < NEXP; e++) acc = fmaf(ec[s * NEXP + e], w[e], acc);
        g_bias0[s * 640 + j] = acc;
    }
}

// ---------------------------------------------------------------------------
// FP16 grouped GEMM: 128x128 CTA tile, K-tile 64, 3-stage cp.async pipeline.
// 8 warps (4M x 2N), each 32x64 via m16n8k16. ldmatrix frag loads.
// ---------------------------------------------------------------------------
#define KTILE 64
#define SA_H 72              // 64 + 8 pad (halves)
#define SB_H 136             // 128 + 8 pad (halves)
#define STAGES 3
#define A_STAGE (128 * SA_H) // 9216 halves
#define B_STAGE (KTILE * SB_H) // 8704 halves
#define SMEM_HALVES (STAGES * (A_STAGE + B_STAGE))
#define SMEM_BYTES (SMEM_HALVES * 2 + 512)

__device__ __forceinline__ void mma_f16(float* d, const uint32_t* a, const uint32_t* b) {
    asm volatile(
        "mma.sync.aligned.m16n8k16.row.col.f32.f16.f16.f32 "
        "{%0,%1,%2,%3}, {%4,%5,%6,%7}, {%8,%9}, {%0,%1,%2,%3};\n"
        : "+f"(d[0]), "+f"(d[1]), "+f"(d[2]), "+f"(d[3])
        : "r"(a[0]), "r"(a[1]), "r"(a[2]), "r"(a[3]),
          "r"(b[0]), "r"(b[1]));
}

__device__ __forceinline__ void ldsm_x4(uint32_t* r, uint32_t saddr) {
    asm volatile("ldmatrix.sync.aligned.m8n8.x4.shared.b16 {%0,%1,%2,%3}, [%4];"
        : "=r"(r[0]), "=r"(r[1]), "=r"(r[2]), "=r"(r[3]) : "r"(saddr));
}

__device__ __forceinline__ void ldsm_x4_t(uint32_t* r, uint32_t saddr) {
    asm volatile("ldmatrix.sync.aligned.m8n8.x4.trans.shared.b16 {%0,%1,%2,%3}, [%4];"
        : "=r"(r[0]), "=r"(r[1]), "=r"(r[2]), "=r"(r[3]) : "r"(saddr));
}

__device__ __forceinline__ void cp16(void* dst, const void* src) {
    uint32_t sa = (uint32_t)__cvta_generic_to_shared(dst);
    asm volatile("cp.async.cg.shared.global [%0], [%1], 16;\n" :: "r"(sa), "l"(src));
}

__device__ __forceinline__ void cp16z(void* dst, const void* src, int sz) {
    uint32_t sa = (uint32_t)__cvta_generic_to_shared(dst);
    asm volatile("cp.async.cg.shared.global [%0], [%1], 16, %2;\n" :: "r"(sa), "l"(src), "r"(sz));
}

template <int SEG>
__global__ __launch_bounds__(256, 1) void gemm_kernel(float* __restrict__ out) {
    constexpr int K    = (SEG == 0) ? 640 : (SEG == 1) ? 1024 : 768;
    constexpr int N    = K;
    constexpr int XOFF = (SEG == 0) ? 0 : (SEG == 1) ? 640 : 1664;
    constexpr int OOFF = XOFF;
    constexpr int KT   = K / KTILE;

    int ti = blockIdx.y;
    if (ti >= g_ntiles) return;
    const int sys = g_tsys[ti];
    const int m0  = g_tm0[ti];
    const int cnt = g_cnt[sys];
    const int n0  = blockIdx.x * 128;

    const __half* Bw = (SEG == 0) ? g_B0 : (SEG == 1) ? g_B1 : g_B2;
    const __half* Bsys = Bw + (size_t)sys * K * N;

    extern __shared__ __half smh[];
    __half* sA = smh;                       // [STAGES][128][SA_H]
    __half* sB = smh + STAGES * A_STAGE;    // [STAGES][KTILE][SB_H]
    int*    sE = (int*)(smh + SMEM_HALVES); // [128]

    const int tid = threadIdx.x;

    if (tid < 128) {
        int idx = m0 + tid;
        sE[tid] = (idx < cnt) ? g_list[sys * NEDGES + idx] : -1;
    }
    __syncthreads();

    auto load_tile = [&](int kt, int buf) {
        __half* aBuf = sA + buf * A_STAGE;
        __half* bBuf = sB + buf * B_STAGE;
        // A: 128 rows x 64 halves = 1024 x 16B chunks (8 halves each)
#pragma unroll
        for (int i = 0; i < 4; i++) {
            int c = tid + i * 256;
            int row = c >> 3, cc = c & 7;
            int e = sE[row];
            const __half* src = g_xh +
                ((e >= 0) ? ((size_t)e * ROWF + XOFF) : (size_t)0) + kt * KTILE + cc * 8;
            cp16z(aBuf + row * SA_H + cc * 8, src, (e >= 0) ? 16 : 0);
        }
        // B: 64 k-rows x 128 halves = 1024 x 16B chunks
#pragma unroll
        for (int i = 0; i < 4; i++) {
            int c = tid + i * 256;
            int k = c >> 4, n8 = c & 15;
            const __half* src = Bsys + (size_t)(kt * KTILE + k) * N + n0 + n8 * 8;
            cp16(bBuf + k * SB_H + n8 * 8, src);
        }
        asm volatile("cp.async.commit_group;\n" ::);
    };

    const int lane = tid & 31, warp = tid >> 5;
    const int wm = warp & 3, wn = warp >> 2;     // 4 M-warps x 2 N-warps
    const int gid = lane >> 2, tig = lane & 3;
    const int l15 = lane & 15, lhi = lane >> 4;

    float acc[2][8][4];
#pragma unroll
    for (int a = 0; a < 2; a++)
#pragma unroll
        for (int b = 0; b < 8; b++)
#pragma unroll
            for (int c = 0; c < 4; c++) acc[a][b][c] = 0.f;

    const uint32_t sA_u = (uint32_t)__cvta_generic_to_shared(sA);
    const uint32_t sB_u = (uint32_t)__cvta_generic_to_shared(sB);

    // per-thread ldmatrix byte offsets (within a stage)
    uint32_t aoff[2], boff[4];
#pragma unroll
    for (int mt = 0; mt < 2; mt++)
        aoff[mt] = ((wm * 32 + mt * 16 + l15) * SA_H + lhi * 8) * 2;
#pragma unroll
    for (int p = 0; p < 4; p++)
        boff[p] = (l15 * SB_H + wn * 64 + p * 16 + lhi * 8) * 2;

    // prologue: 2 stages in flight
    load_tile(0, 0);
    load_tile(1, 1);

    for (int kt = 0; kt < KT; kt++) {
        asm volatile("cp.async.wait_group 1;\n" ::);
        __syncthreads();
        if (kt + 2 < KT) load_tile(kt + 2, (kt + 2) % STAGES);

        const int buf = kt % STAGES;
        const uint32_t aB = sA_u + buf * A_STAGE * 2;
        const uint32_t bB = sB_u + buf * B_STAGE * 2;

#pragma unroll
        for (int ks = 0; ks < 4; ks++) {
            uint32_t af[2][4], bf[8][2];
#pragma unroll
            for (int mt = 0; mt < 2; mt++)
                ldsm_x4(af[mt], aB + aoff[mt] + ks * 16 * 2);
#pragma unroll
            for (int p = 0; p < 4; p++) {
                uint32_t r[4];
                ldsm_x4_t(r, bB + boff[p] + ks * 16 * SB_H * 2);
                bf[2 * p][0] = r[0]; bf[2 * p][1] = r[1];
                bf[2 * p + 1][0] = r[2]; bf[2 * p + 1][1] = r[3];
            }
#pragma unroll
            for (int mt = 0; mt < 2; mt++)
#pragma unroll
                for (int nt = 0; nt < 8; nt++)
                    mma_f16(acc[mt][nt], af[mt], bf[nt]);
        }
        __syncthreads();
    }

    // epilogue: scatter rows by edge id, fold bias for SEG 0
#pragma unroll
    for (int mt = 0; mt < 2; mt++) {
        int r0 = wm * 32 + mt * 16 + gid;
        int e0 = sE[r0], e1 = sE[r0 + 8];
#pragma unroll
        for (int nt = 0; nt < 8; nt++) {
            int col = n0 + wn * 64 + nt * 8 + tig * 2;
            float b0 = 0.f, b1 = 0.f;
            if (SEG == 0) {
                b0 = g_bias0[sys * 640 + col];
                b1 = g_bias0[sys * 640 + col + 1];
            }
            if (e0 >= 0) {
                float2 v;
                v.x = acc[mt][nt][0] + b0;
                v.y = acc[mt][nt][1] + b1;
                *(float2*)(out + (size_t)e0 * ROWF + OOFF + col) = v;
            }
            if (e1 >= 0) {
                float2 v;
                v.x = acc[mt][nt][2] + b0;
                v.y = acc[mt][nt][3] + b1;
                *(float2*)(out + (size_t)e1 * ROWF + OOFF + col) = v;
            }
        }
    }
}

// ---------------------------------------------------------------------------
extern "C" void kernel_launch(void* const* d_in, const int* in_sizes, int n_in,
                              void* d_out, int out_size) {
    const float* x   = (const float*)d_in[0];
    const float* ec  = (const float*)d_in[2];
    const int*   eb  = (const int*)d_in[3];
    const float* Wm0 = (const float*)d_in[4];
    const float* bm0 = (const float*)d_in[5];
    const float* Wm1 = (const float*)d_in[6];
    const float* Wm2 = (const float*)d_in[7];
    float* out = (float*)d_out;

    cudaFuncSetAttribute(gemm_kernel<0>, cudaFuncAttributeMaxDynamicSharedMemorySize, SMEM_BYTES);
    cudaFuncSetAttribute(gemm_kernel<1>, cudaFuncAttributeMaxDynamicSharedMemorySize, SMEM_BYTES);
    cudaFuncSetAttribute(gemm_kernel<2>, cudaFuncAttributeMaxDynamicSharedMemorySize, SMEM_BYTES);

    reset_kernel<<<1, 32>>>();
    bucket_kernel<<<(NEDGES + 255) / 256, 256>>>(eb);
    plan_kernel<<<1, 32>>>();

    cvt_kernel<<<(NEDGES * ROWF / 4 + 255) / 256, 256>>>(x);

    mix_kernel<0><<<(640 * 640 / 4 + 255) / 256, 256>>>(Wm0, ec);
    mix_kernel<1><<<(1024 * 1024 / 4 + 255) / 256, 256>>>(Wm1, ec);
    mix_kernel<2><<<(768 * 768 / 4 + 255) / 256, 256>>>(Wm2, ec);
    biasmix_kernel<<<3, 256>>>(bm0, ec);

    gemm_kernel<0><<<dim3(640 / 128, MAX_TILES), 256, SMEM_BYTES>>>(out);
    gemm_kernel<1><<<dim3(1024 / 128, MAX_TILES), 256, SMEM_BYTES>>>(out);
    gemm_kernel<2><<<dim3(768 / 128, MAX_TILES), 256, SMEM_BYTES>>>(out);
}

// round 5
// speedup vs baseline: 1.9235x; 1.0836x over previous
#include <cuda_runtime.h>
#include <cuda_fp16.h>
#include <cstdint>

// ---------------------------------------------------------------------------
// SO2ConvolutionMoE, FP16 mma.sync version (tcgen05 unavailable: harness PTX
// targets compute_103 without the 'a' feature set).
//   - premix per-system expert weights (fp32 accum -> fp16), SO(2) recombine
//     folded into B' = [[Wl, Wr], [-Wr, Wl]]
//   - pre-convert x to fp16 once
//   - grouped GEMMs: 128 x NTILE CTA tiles (NTILE=128 seg0 / 256 seg1,2),
//     warp tile 64 x (NTILE/4), m16n8k16, ldmatrix, 3-stage cp.async.
// ---------------------------------------------------------------------------

#define NEDGES 12288
#define NSYS   16
#define NEXP   8
#define ROWF   2432
#define MAX_TILES 112

__device__ __half g_B0[(size_t)NSYS * 640 * 640];     // [K][N]
__device__ __half g_B1[(size_t)NSYS * 1024 * 1024];
__device__ __half g_B2[(size_t)NSYS * 768 * 768];
__device__ float  g_bias0[NSYS * 640];
__device__ __half g_xh[(size_t)NEDGES * ROWF];
__device__ int    g_list[NSYS * NEDGES];
__device__ int    g_cnt[NSYS];
__device__ int    g_tsys[MAX_TILES];
__device__ int    g_tm0[MAX_TILES];
__device__ int    g_ntiles;

__device__ __forceinline__ uint32_t h2_as_u32(__half2 h) {
    return *reinterpret_cast<const uint32_t*>(&h);
}

// ---------------------------------------------------------------------------
__global__ void reset_kernel() {
    if (threadIdx.x < NSYS) g_cnt[threadIdx.x] = 0;
}

__global__ void bucket_kernel(const int* __restrict__ eb) {
    int i = blockIdx.x * blockDim.x + threadIdx.x;
    if (i < NEDGES) {
        int s = eb[i];
        int p = atomicAdd(&g_cnt[s], 1);
        g_list[s * NEDGES + p] = i;
    }
}

__global__ void plan_kernel() {
    if (threadIdx.x == 0) {
        int nt = 0;
        for (int s = 0; s < NSYS; s++) {
            int c = g_cnt[s];
            for (int m0 = 0; m0 < c; m0 += 128) {
                g_tsys[nt] = s;
                g_tm0[nt]  = m0;
                nt++;
            }
        }
        g_ntiles = nt;
    }
}

__global__ void cvt_kernel(const float* __restrict__ x) {
    const int total4 = NEDGES * ROWF / 4;
    int i = blockIdx.x * blockDim.x + threadIdx.x;
    if (i >= total4) return;
    float4 v = ((const float4*)x)[i];
    uint2 u;
    u.x = h2_as_u32(__floats2half2_rn(v.x, v.y));
    u.y = h2_as_u32(__floats2half2_rn(v.z, v.w));
    *reinterpret_cast<uint2*>(g_xh + (size_t)i * 4) = u;
}

// ---------------------------------------------------------------------------
// Weight mixing (vectorized by 4 cols, fp16 output, [K][N] layout)
// ---------------------------------------------------------------------------
template <int MODE>
__global__ void mix_kernel(const float* __restrict__ W, const float* __restrict__ ec) {
    constexpr int Kin   = (MODE == 0) ? 640 : (MODE == 1) ? 512 : 384;
    constexpr int Nw    = (MODE == 0) ? 640 : (MODE == 1) ? 1024 : 768;
    constexpr int SO2   = (MODE == 0) ? 0 : 1;
    constexpr int KTOT  = SO2 ? 2 * Kin : Kin;
    constexpr int TOTAL = KTOT * Nw;
    constexpr int N4    = Nw / 4;

    __half* Bd = (MODE == 0) ? g_B0 : (MODE == 1) ? g_B1 : g_B2;

    __shared__ float sec[NSYS * NEXP];
    if (threadIdx.x < NSYS * NEXP) sec[threadIdx.x] = ec[threadIdx.x];
    __syncthreads();

    int idx4 = blockIdx.x * blockDim.x + threadIdx.x;
    if (idx4 >= TOTAL / 4) return;
    int k  = idx4 / N4;
    int jj = idx4 - k * N4;

    float sign = 1.f;
    size_t src4;
    if (!SO2 || k < Kin) {
        src4 = (size_t)k * N4 + jj;
    } else {
        int kk = k - Kin;
        int Nh4 = N4 >> 1;
        if (jj < Nh4) { src4 = (size_t)kk * N4 + Nh4 + jj; sign = -1.f; }
        else          { src4 = (size_t)kk * N4 + (jj - Nh4); }
    }

    const size_t esz4 = (size_t)Kin * N4;
    float4 w[NEXP];
#pragma unroll
    for (int e = 0; e < NEXP; e++) w[e] = ((const float4*)W)[e * esz4 + src4];

#pragma unroll
    for (int s = 0; s < NSYS; s++) {
        float4 a = make_float4(0.f, 0.f, 0.f, 0.f);
#pragma unroll
        for (int e = 0; e < NEXP; e++) {
            float c = sec[s * NEXP + e];
            a.x = fmaf(c, w[e].x, a.x); a.y = fmaf(c, w[e].y, a.y);
            a.z = fmaf(c, w[e].z, a.z); a.w = fmaf(c, w[e].w, a.w);
        }
        uint2 u;
        u.x = h2_as_u32(__floats2half2_rn(sign * a.x, sign * a.y));
        u.y = h2_as_u32(__floats2half2_rn(sign * a.z, sign * a.w));
        *reinterpret_cast<uint2*>(Bd + (size_t)s * TOTAL + (size_t)idx4 * 4) = u;
    }
}

__global__ void biasmix_kernel(const float* __restrict__ b, const float* __restrict__ ec) {
    int j = blockIdx.x * blockDim.x + threadIdx.x;
    if (j >= 640) return;
    float w[NEXP];
#pragma unroll
    for (int e = 0; e < NEXP; e++) w[e] = b[e * 640 + j];
#pragma unroll
    for (int s = 0; s < NSYS; s++) {
        float acc = 0.f;
#pragma unroll
        for (int e = 0; e < NEXP; e++) acc = fmaf(ec[s * NEXP + e], w[e], acc);
        g_bias0[s * 640 + j] = acc;
    }
}

// ---------------------------------------------------------------------------
// FP16 grouped GEMM: 128 x NTILE CTA tile, KTILE=64, 3-stage cp.async.
// 8 warps as 2M x 4N, warp tile 64 x (NTILE/4).
// ---------------------------------------------------------------------------
#define KTILE 64
#define SA_H 72              // 64 + 8 pad (halves)
#define STAGES 3
#define A_STAGE (128 * SA_H)

__device__ __forceinline__ void mma_f16(float* d, const uint32_t* a, const uint32_t* b) {
    asm volatile(
        "mma.sync.aligned.m16n8k16.row.col.f32.f16.f16.f32 "
        "{%0,%1,%2,%3}, {%4,%5,%6,%7}, {%8,%9}, {%0,%1,%2,%3};\n"
        : "+f"(d[0]), "+f"(d[1]), "+f"(d[2]), "+f"(d[3])
        : "r"(a[0]), "r"(a[1]), "r"(a[2]), "r"(a[3]),
          "r"(b[0]), "r"(b[1]));
}

__device__ __forceinline__ void ldsm_x4(uint32_t* r, uint32_t saddr) {
    asm volatile("ldmatrix.sync.aligned.m8n8.x4.shared.b16 {%0,%1,%2,%3}, [%4];"
        : "=r"(r[0]), "=r"(r[1]), "=r"(r[2]), "=r"(r[3]) : "r"(saddr));
}

__device__ __forceinline__ void ldsm_x4_t(uint32_t* r, uint32_t saddr) {
    asm volatile("ldmatrix.sync.aligned.m8n8.x4.trans.shared.b16 {%0,%1,%2,%3}, [%4];"
        : "=r"(r[0]), "=r"(r[1]), "=r"(r[2]), "=r"(r[3]) : "r"(saddr));
}

__device__ __forceinline__ void cp16(void* dst, const void* src) {
    uint32_t sa = (uint32_t)__cvta_generic_to_shared(dst);
    asm volatile("cp.async.cg.shared.global [%0], [%1], 16;\n" :: "r"(sa), "l"(src));
}

__device__ __forceinline__ void cp16z(void* dst, const void* src, int sz) {
    uint32_t sa = (uint32_t)__cvta_generic_to_shared(dst);
    asm volatile("cp.async.cg.shared.global [%0], [%1], 16, %2;\n" :: "r"(sa), "l"(src), "r"(sz));
}

template <int SEG, int NTILE>
__global__ __launch_bounds__(256, 1) void gemm_kernel(float* __restrict__ out) {
    constexpr int K    = (SEG == 0) ? 640 : (SEG == 1) ? 1024 : 768;
    constexpr int N    = K;
    constexpr int XOFF = (SEG == 0) ? 0 : (SEG == 1) ? 640 : 1664;
    constexpr int OOFF = XOFF;
    constexpr int KT   = K / KTILE;
    constexpr int WN   = NTILE / 4;        // warp N extent (32 or 64)
    constexpr int NFR  = WN / 8;           // n-frags per warp (4 or 8)
    constexpr int NPAIR = WN / 16;         // ldsm.x4.trans per ks (2 or 4)
    constexpr int SB_H = NTILE + 8;
    constexpr int B_STAGE = KTILE * SB_H;
    constexpr int SMEM_HALVES = STAGES * (A_STAGE + B_STAGE);

    int ti = blockIdx.y;
    if (ti >= g_ntiles) return;
    const int sys = g_tsys[ti];
    const int m0  = g_tm0[ti];
    const int cnt = g_cnt[sys];
    const int n0  = blockIdx.x * NTILE;

    const __half* Bw = (SEG == 0) ? g_B0 : (SEG == 1) ? g_B1 : g_B2;
    const __half* Bsys = Bw + (size_t)sys * K * N;

    extern __shared__ __half smh[];
    __half* sA = smh;                       // [STAGES][128][SA_H]
    __half* sB = smh + STAGES * A_STAGE;    // [STAGES][KTILE][SB_H]
    int*    sE = (int*)(smh + SMEM_HALVES); // [128]

    const int tid = threadIdx.x;

    if (tid < 128) {
        int idx = m0 + tid;
        sE[tid] = (idx < cnt) ? g_list[sys * NEDGES + idx] : -1;
    }
    __syncthreads();

    auto load_tile = [&](int kt, int buf) {
        __half* aBuf = sA + buf * A_STAGE;
        __half* bBuf = sB + buf * B_STAGE;
        // A: 128 rows x 64 halves = 1024 x 16B chunks
#pragma unroll
        for (int i = 0; i < 4; i++) {
            int c = tid + i * 256;
            int row = c >> 3, cc = c & 7;
            int e = sE[row];
            const __half* src = g_xh +
                ((e >= 0) ? ((size_t)e * ROWF + XOFF) : (size_t)0) + kt * KTILE + cc * 8;
            cp16z(aBuf + row * SA_H + cc * 8, src, (e >= 0) ? 16 : 0);
        }
        // B: KTILE rows x NTILE halves
#pragma unroll
        for (int i = 0; i < KTILE * NTILE / 8 / 256; i++) {
            int c = tid + i * 256;
            int k = c / (NTILE / 8), n8 = c % (NTILE / 8);
            const __half* src = Bsys + (size_t)(kt * KTILE + k) * N + n0 + n8 * 8;
            cp16(bBuf + k * SB_H + n8 * 8, src);
        }
        asm volatile("cp.async.commit_group;\n" ::);
    };

    const int lane = tid & 31, warp = tid >> 5;
    const int wm = warp & 1, wn = warp >> 1;     // 2 M-warps x 4 N-warps
    const int gid = lane >> 2, tig = lane & 3;
    const int l15 = lane & 15, lhi = lane >> 4;

    float acc[4][NFR][4];
#pragma unroll
    for (int a = 0; a < 4; a++)
#pragma unroll
        for (int b = 0; b < NFR; b++)
#pragma unroll
            for (int c = 0; c < 4; c++) acc[a][b][c] = 0.f;

    const uint32_t sA_u = (uint32_t)__cvta_generic_to_shared(sA);
    const uint32_t sB_u = (uint32_t)__cvta_generic_to_shared(sB);

    uint32_t aoff[4], boff[NPAIR];
#pragma unroll
    for (int mt = 0; mt < 4; mt++)
        aoff[mt] = ((wm * 64 + mt * 16 + l15) * SA_H + lhi * 8) * 2;
#pragma unroll
    for (int p = 0; p < NPAIR; p++)
        boff[p] = (l15 * SB_H + wn * WN + p * 16 + lhi * 8) * 2;

    // prologue: 2 stages in flight
    load_tile(0, 0);
    load_tile(1, 1);

    for (int kt = 0; kt < KT; kt++) {
        if (kt + 1 < KT) asm volatile("cp.async.wait_group 1;\n" ::);
        else             asm volatile("cp.async.wait_group 0;\n" ::);
        __syncthreads();
        if (kt + 2 < KT) load_tile(kt + 2, (kt + 2) % STAGES);

        const int buf = kt % STAGES;
        const uint32_t aB = sA_u + buf * A_STAGE * 2;
        const uint32_t bB = sB_u + buf * B_STAGE * 2;

#pragma unroll
        for (int ks = 0; ks < 4; ks++) {
            uint32_t af[4][4], bf[NFR][2];
#pragma unroll
            for (int mt = 0; mt < 4; mt++)
                ldsm_x4(af[mt], aB + aoff[mt] + ks * 16 * 2);
#pragma unroll
            for (int p = 0; p < NPAIR; p++) {
                uint32_t r[4];
                ldsm_x4_t(r, bB + boff[p] + ks * 16 * SB_H * 2);
                bf[2 * p][0] = r[0]; bf[2 * p][1] = r[1];
                bf[2 * p + 1][0] = r[2]; bf[2 * p + 1][1] = r[3];
            }
#pragma unroll
            for (int mt = 0; mt < 4; mt++)
#pragma unroll
                for (int nt = 0; nt < NFR; nt++)
                    mma_f16(acc[mt][nt], af[mt], bf[nt]);
        }
        __syncthreads();
    }

    // epilogue: scatter rows by edge id, fold bias for SEG 0
#pragma unroll
    for (int mt = 0; mt < 4; mt++) {
        int r0 = wm * 64 + mt * 16 + gid;
        int e0 = sE[r0], e1 = sE[r0 + 8];
#pragma unroll
        for (int nt = 0; nt < NFR; nt++) {
            int col = n0 + wn * WN + nt * 8 + tig * 2;
            float b0 = 0.f, b1 = 0.f;
            if (SEG == 0) {
                b0 = g_bias0[sys * 640 + col];
                b1 = g_bias0[sys * 640 + col + 1];
            }
            if (e0 >= 0) {
                float2 v;
                v.x = acc[mt][nt][0] + b0;
                v.y = acc[mt][nt][1] + b1;
                *(float2*)(out + (size_t)e0 * ROWF + OOFF + col) = v;
            }
            if (e1 >= 0) {
                float2 v;
                v.x = acc[mt][nt][2] + b0;
                v.y = acc[mt][nt][3] + b1;
                *(float2*)(out + (size_t)e1 * ROWF + OOFF + col) = v;
            }
        }
    }
}

// ---------------------------------------------------------------------------
extern "C" void kernel_launch(void* const* d_in, const int* in_sizes, int n_in,
                              void* d_out, int out_size) {
    const float* x   = (const float*)d_in[0];
    const float* ec  = (const float*)d_in[2];
    const int*   eb  = (const int*)d_in[3];
    const float* Wm0 = (const float*)d_in[4];
    const float* bm0 = (const float*)d_in[5];
    const float* Wm1 = (const float*)d_in[6];
    const float* Wm2 = (const float*)d_in[7];
    float* out = (float*)d_out;

    constexpr int SM128 = (STAGES * (A_STAGE + KTILE * (128 + 8))) * 2 + 512;
    constexpr int SM256 = (STAGES * (A_STAGE + KTILE * (256 + 8))) * 2 + 512;

    cudaFuncSetAttribute(gemm_kernel<0, 128>, cudaFuncAttributeMaxDynamicSharedMemorySize, SM128);
    cudaFuncSetAttribute(gemm_kernel<1, 256>, cudaFuncAttributeMaxDynamicSharedMemorySize, SM256);
    cudaFuncSetAttribute(gemm_kernel<2, 256>, cudaFuncAttributeMaxDynamicSharedMemorySize, SM256);

    reset_kernel<<<1, 32>>>();
    bucket_kernel<<<(NEDGES + 255) / 256, 256>>>(eb);
    plan_kernel<<<1, 32>>>();

    cvt_kernel<<<(NEDGES * ROWF / 4 + 255) / 256, 256>>>(x);

    mix_kernel<0><<<(640 * 640 / 4 + 255) / 256, 256>>>(Wm0, ec);
    mix_kernel<1><<<(1024 * 1024 / 4 + 255) / 256, 256>>>(Wm1, ec);
    mix_kernel<2><<<(768 * 768 / 4 + 255) / 256, 256>>>(Wm2, ec);
    biasmix_kernel<<<3, 256>>>(bm0, ec);

    gemm_kernel<0, 128><<<dim3(640 / 128, MAX_TILES), 256, SM128>>>(out);
    gemm_kernel<1, 256><<<dim3(1024 / 256, MAX_TILES), 256, SM256>>>(out);
    gemm_kernel<2, 256><<<dim3(768 / 256, MAX_TILES), 256, SM256>>>(out);
}

// round 6
// speedup vs baseline: 2.3629x; 1.2284x over previous
#include <cuda_runtime.h>
#include <cuda_fp16.h>
#include <cstdint>

// ---------------------------------------------------------------------------
// SO2ConvolutionMoE, FP16 mma.sync, single fused GEMM kernel:
//   - per-system premixed weights (SO(2) recombination folded into B)
//   - x pre-converted fp16
//   - ONE kernel for all 3 segments: global tile list (seg,sys,m0,n0),
//     longest-K-first order, 128x128 CTA tiles, warp 64x32, 3-stage cp.async,
//     2 CTAs/SM for cross-CTA tensor-pipe overlap.
// ---------------------------------------------------------------------------

#define NEDGES 12288
#define NSYS   16
#define NEXP   8
#define ROWF   2432
#define MAX_GT (112 * 19)     // <= 2128 CTA tiles

__device__ __half g_B0[(size_t)NSYS * 640 * 640];     // [K][N]
__device__ __half g_B1[(size_t)NSYS * 1024 * 1024];
__device__ __half g_B2[(size_t)NSYS * 768 * 768];
__device__ float  g_bias0[NSYS * 640];
__device__ __half g_xh[(size_t)NEDGES * ROWF];
__device__ int    g_list[NSYS * NEDGES];
__device__ int    g_cnt[NSYS];
__device__ int    g_gdesc[MAX_GT];     // packed: seg(2) | sys(4) | nb(4) | m0(22)
__device__ int    g_ngt;

__device__ __forceinline__ uint32_t h2_as_u32(__half2 h) {
    return *reinterpret_cast<const uint32_t*>(&h);
}

// ---------------------------------------------------------------------------
__global__ void reset_kernel() {
    if (threadIdx.x < NSYS) g_cnt[threadIdx.x] = 0;
}

__global__ void bucket_kernel(const int* __restrict__ eb) {
    int i = blockIdx.x * blockDim.x + threadIdx.x;
    if (i < NEDGES) {
        int s = eb[i];
        int p = atomicAdd(&g_cnt[s], 1);
        g_list[s * NEDGES + p] = i;
    }
}

__global__ void plan_kernel() {
    if (threadIdx.x == 0) {
        const int segorder[3] = {1, 2, 0};     // longest K first
        const int nbs[3] = {5, 8, 6};          // n-blocks per seg (N/128)
        int ng = 0;
        for (int so = 0; so < 3; so++) {
            int seg = segorder[so];
            for (int s = 0; s < NSYS; s++) {
                int c = g_cnt[s];
                for (int m0 = 0; m0 < c; m0 += 128)
                    for (int nb = 0; nb < nbs[seg]; nb++)
                        g_gdesc[ng++] = (seg << 30) | (s << 26) | (nb << 22) | m0;
            }
        }
        g_ngt = ng;
    }
}

__global__ void cvt_kernel(const float* __restrict__ x) {
    const int total4 = NEDGES * ROWF / 4;
    int i = blockIdx.x * blockDim.x + threadIdx.x;
    if (i >= total4) return;
    float4 v = ((const float4*)x)[i];
    uint2 u;
    u.x = h2_as_u32(__floats2half2_rn(v.x, v.y));
    u.y = h2_as_u32(__floats2half2_rn(v.z, v.w));
    *reinterpret_cast<uint2*>(g_xh + (size_t)i * 4) = u;
}

// ---------------------------------------------------------------------------
// Weight mixing (vectorized by 4 cols, fp16 output, [K][N] layout)
// ---------------------------------------------------------------------------
template <int MODE>
__global__ void mix_kernel(const float* __restrict__ W, const float* __restrict__ ec) {
    constexpr int Kin   = (MODE == 0) ? 640 : (MODE == 1) ? 512 : 384;
    constexpr int Nw    = (MODE == 0) ? 640 : (MODE == 1) ? 1024 : 768;
    constexpr int SO2   = (MODE == 0) ? 0 : 1;
    constexpr int KTOT  = SO2 ? 2 * Kin : Kin;
    constexpr int TOTAL = KTOT * Nw;
    constexpr int N4    = Nw / 4;

    __half* Bd = (MODE == 0) ? g_B0 : (MODE == 1) ? g_B1 : g_B2;

    __shared__ float sec[NSYS * NEXP];
    if (threadIdx.x < NSYS * NEXP) sec[threadIdx.x] = ec[threadIdx.x];
    __syncthreads();

    int idx4 = blockIdx.x * blockDim.x + threadIdx.x;
    if (idx4 >= TOTAL / 4) return;
    int k  = idx4 / N4;
    int jj = idx4 - k * N4;

    float sign = 1.f;
    size_t src4;
    if (!SO2 || k < Kin) {
        src4 = (size_t)k * N4 + jj;
    } else {
        int kk = k - Kin;
        int Nh4 = N4 >> 1;
        if (jj < Nh4) { src4 = (size_t)kk * N4 + Nh4 + jj; sign = -1.f; }
        else          { src4 = (size_t)kk * N4 + (jj - Nh4); }
    }

    const size_t esz4 = (size_t)Kin * N4;
    float4 w[NEXP];
#pragma unroll
    for (int e = 0; e < NEXP; e++) w[e] = ((const float4*)W)[e * esz4 + src4];

#pragma unroll
    for (int s = 0; s < NSYS; s++) {
        float4 a = make_float4(0.f, 0.f, 0.f, 0.f);
#pragma unroll
        for (int e = 0; e < NEXP; e++) {
            float c = sec[s * NEXP + e];
            a.x = fmaf(c, w[e].x, a.x); a.y = fmaf(c, w[e].y, a.y);
            a.z = fmaf(c, w[e].z, a.z); a.w = fmaf(c, w[e].w, a.w);
        }
        uint2 u;
        u.x = h2_as_u32(__floats2half2_rn(sign * a.x, sign * a.y));
        u.y = h2_as_u32(__floats2half2_rn(sign * a.z, sign * a.w));
        *reinterpret_cast<uint2*>(Bd + (size_t)s * TOTAL + (size_t)idx4 * 4) = u;
    }
}

__global__ void biasmix_kernel(const float* __restrict__ b, const float* __restrict__ ec) {
    int j = blockIdx.x * blockDim.x + threadIdx.x;
    if (j >= 640) return;
    float w[NEXP];
#pragma unroll
    for (int e = 0; e < NEXP; e++) w[e] = b[e * 640 + j];
#pragma unroll
    for (int s = 0; s < NSYS; s++) {
        float acc = 0.f;
#pragma unroll
        for (int e = 0; e < NEXP; e++) acc = fmaf(ec[s * NEXP + e], w[e], acc);
        g_bias0[s * 640 + j] = acc;
    }
}

// ---------------------------------------------------------------------------
// Fused FP16 grouped GEMM: 128x128 CTA tile, KTILE=64, 3-stage cp.async,
// 8 warps as 2M x 4N (warp tile 64x32), 2 CTAs/SM.
// ---------------------------------------------------------------------------
#define KTILE 64
#define SA_H 72              // 64 + 8 pad (halves)
#define SB_H 136             // 128 + 8 pad (halves)
#define STAGES 3
#define A_STAGE (128 * SA_H)
#define B_STAGE (KTILE * SB_H)
#define SMEM_HALVES (STAGES * (A_STAGE + B_STAGE))
#define SMEM_BYTES (SMEM_HALVES * 2 + 512)

__device__ __forceinline__ void mma_f16(float* d, const uint32_t* a, const uint32_t* b) {
    asm volatile(
        "mma.sync.aligned.m16n8k16.row.col.f32.f16.f16.f32 "
        "{%0,%1,%2,%3}, {%4,%5,%6,%7}, {%8,%9}, {%0,%1,%2,%3};\n"
        : "+f"(d[0]), "+f"(d[1]), "+f"(d[2]), "+f"(d[3])
        : "r"(a[0]), "r"(a[1]), "r"(a[2]), "r"(a[3]),
          "r"(b[0]), "r"(b[1]));
}

__device__ __forceinline__ void ldsm_x4(uint32_t* r, uint32_t saddr) {
    asm volatile("ldmatrix.sync.aligned.m8n8.x4.shared.b16 {%0,%1,%2,%3}, [%4];"
        : "=r"(r[0]), "=r"(r[1]), "=r"(r[2]), "=r"(r[3]) : "r"(saddr));
}

__device__ __forceinline__ void ldsm_x4_t(uint32_t* r, uint32_t saddr) {
    asm volatile("ldmatrix.sync.aligned.m8n8.x4.trans.shared.b16 {%0,%1,%2,%3}, [%4];"
        : "=r"(r[0]), "=r"(r[1]), "=r"(r[2]), "=r"(r[3]) : "r"(saddr));
}

__device__ __forceinline__ void cp16(void* dst, const void* src) {
    uint32_t sa = (uint32_t)__cvta_generic_to_shared(dst);
    asm volatile("cp.async.cg.shared.global [%0], [%1], 16;\n" :: "r"(sa), "l"(src));
}

__device__ __forceinline__ void cp16z(void* dst, const void* src, int sz) {
    uint32_t sa = (uint32_t)__cvta_generic_to_shared(dst);
    asm volatile("cp.async.cg.shared.global [%0], [%1], 16, %2;\n" :: "r"(sa), "l"(src), "r"(sz));
}

__global__ __launch_bounds__(256, 2) void gemm_fused(float* __restrict__ out) {
    const int ti = blockIdx.x;
    if (ti >= g_ngt) return;
    const int d   = g_gdesc[ti];
    const int seg = (d >> 30) & 3;
    const int sys = (d >> 26) & 15;
    const int n0  = ((d >> 22) & 15) * 128;
    const int m0  = d & 0x3FFFFF;
    const int cnt = g_cnt[sys];

    const int K    = (seg == 0) ? 640 : (seg == 1) ? 1024 : 768;
    const int XOFF = (seg == 0) ? 0 : (seg == 1) ? 640 : 1664;
    const int KT   = K / KTILE;
    const __half* Bsys =
        ((seg == 0) ? g_B0 : (seg == 1) ? g_B1 : g_B2) + (size_t)sys * K * K;

    extern __shared__ __half smh[];
    __half* sA = smh;                       // [STAGES][128][SA_H]
    __half* sB = smh + STAGES * A_STAGE;    // [STAGES][KTILE][SB_H]
    int*    sE = (int*)(smh + SMEM_HALVES); // [128]

    const int tid = threadIdx.x;

    if (tid < 128) {
        int idx = m0 + tid;
        sE[tid] = (idx < cnt) ? g_list[sys * NEDGES + idx] : -1;
    }
    __syncthreads();

    auto load_tile = [&](int kt, int buf) {
        __half* aBuf = sA + buf * A_STAGE;
        __half* bBuf = sB + buf * B_STAGE;
        // A: 128 rows x 64 halves = 1024 x 16B chunks
#pragma unroll
        for (int i = 0; i < 4; i++) {
            int c = tid + i * 256;
            int row = c >> 3, cc = c & 7;
            int e = sE[row];
            const __half* src = g_xh +
                ((e >= 0) ? ((size_t)e * ROWF + XOFF) : (size_t)0) + kt * KTILE + cc * 8;
            cp16z(aBuf + row * SA_H + cc * 8, src, (e >= 0) ? 16 : 0);
        }
        // B: 64 k-rows x 128 halves = 1024 x 16B chunks
#pragma unroll
        for (int i = 0; i < 4; i++) {
            int c = tid + i * 256;
            int k = c >> 4, n8 = c & 15;
            const __half* src = Bsys + (size_t)(kt * KTILE + k) * K + n0 + n8 * 8;
            cp16(bBuf + k * SB_H + n8 * 8, src);
        }
        asm volatile("cp.async.commit_group;\n" ::);
    };

    const int lane = tid & 31, warp = tid >> 5;
    const int wm = warp & 1, wn = warp >> 1;     // 2 M-warps x 4 N-warps
    const int gid = lane >> 2, tig = lane & 3;
    const int l15 = lane & 15, lhi = lane >> 4;

    float acc[4][4][4];
#pragma unroll
    for (int a = 0; a < 4; a++)
#pragma unroll
        for (int b = 0; b < 4; b++)
#pragma unroll
            for (int c = 0; c < 4; c++) acc[a][b][c] = 0.f;

    const uint32_t sA_u = (uint32_t)__cvta_generic_to_shared(sA);
    const uint32_t sB_u = (uint32_t)__cvta_generic_to_shared(sB);

    uint32_t aoff[4], boff[2];
#pragma unroll
    for (int mt = 0; mt < 4; mt++)
        aoff[mt] = ((wm * 64 + mt * 16 + l15) * SA_H + lhi * 8) * 2;
#pragma unroll
    for (int p = 0; p < 2; p++)
        boff[p] = (l15 * SB_H + wn * 32 + p * 16 + lhi * 8) * 2;

    // prologue: 2 stages in flight
    load_tile(0, 0);
    load_tile(1, 1);

    for (int kt = 0; kt < KT; kt++) {
        if (kt + 1 < KT) asm volatile("cp.async.wait_group 1;\n" ::);
        else             asm volatile("cp.async.wait_group 0;\n" ::);
        __syncthreads();
        if (kt + 2 < KT) load_tile(kt + 2, (kt + 2) % STAGES);

        const int buf = kt % STAGES;
        const uint32_t aB = sA_u + buf * A_STAGE * 2;
        const uint32_t bB = sB_u + buf * B_STAGE * 2;

#pragma unroll
        for (int ks = 0; ks < 4; ks++) {
            uint32_t af[4][4], bf[4][2];
#pragma unroll
            for (int mt = 0; mt < 4; mt++)
                ldsm_x4(af[mt], aB + aoff[mt] + ks * 16 * 2);
#pragma unroll
            for (int p = 0; p < 2; p++) {
                uint32_t r[4];
                ldsm_x4_t(r, bB + boff[p] + ks * 16 * SB_H * 2);
                bf[2 * p][0] = r[0]; bf[2 * p][1] = r[1];
                bf[2 * p + 1][0] = r[2]; bf[2 * p + 1][1] = r[3];
            }
#pragma unroll
            for (int mt = 0; mt < 4; mt++)
#pragma unroll
                for (int nt = 0; nt < 4; nt++)
                    mma_f16(acc[mt][nt], af[mt], bf[nt]);
        }
        __syncthreads();
    }

    // epilogue: scatter rows by edge id, fold bias for seg 0
#pragma unroll
    for (int mt = 0; mt < 4; mt++) {
        int r0 = wm * 64 + mt * 16 + gid;
        int e0 = sE[r0], e1 = sE[r0 + 8];
#pragma unroll
        for (int nt = 0; nt < 4; nt++) {
            int col = n0 + wn * 32 + nt * 8 + tig * 2;
            float b0 = 0.f, b1 = 0.f;
            if (seg == 0) {
                b0 = g_bias0[sys * 640 + col];
                b1 = g_bias0[sys * 640 + col + 1];
            }
            if (e0 >= 0) {
                float2 v;
                v.x = acc[mt][nt][0] + b0;
                v.y = acc[mt][nt][1] + b1;
                *(float2*)(out + (size_t)e0 * ROWF + XOFF + col) = v;
            }
            if (e1 >= 0) {
                float2 v;
                v.x = acc[mt][nt][2] + b0;
                v.y = acc[mt][nt][3] + b1;
                *(float2*)(out + (size_t)e1 * ROWF + XOFF + col) = v;
            }
        }
    }
}

// ---------------------------------------------------------------------------
extern "C" void kernel_launch(void* const* d_in, const int* in_sizes, int n_in,
                              void* d_out, int out_size) {
    const float* x   = (const float*)d_in[0];
    const float* ec  = (const float*)d_in[2];
    const int*   eb  = (const int*)d_in[3];
    const float* Wm0 = (const float*)d_in[4];
    const float* bm0 = (const float*)d_in[5];
    const float* Wm1 = (const float*)d_in[6];
    const float* Wm2 = (const float*)d_in[7];
    float* out = (float*)d_out;

    cudaFuncSetAttribute(gemm_fused, cudaFuncAttributeMaxDynamicSharedMemorySize, SMEM_BYTES);

    reset_kernel<<<1, 32>>>();
    bucket_kernel<<<(NEDGES + 255) / 256, 256>>>(eb);
    plan_kernel<<<1, 32>>>();

    cvt_kernel<<<(NEDGES * ROWF / 4 + 255) / 256, 256>>>(x);

    mix_kernel<0><<<(640 * 640 / 4 + 255) / 256, 256>>>(Wm0, ec);
    mix_kernel<1><<<(1024 * 1024 / 4 + 255) / 256, 256>>>(Wm1, ec);
    mix_kernel<2><<<(768 * 768 / 4 + 255) / 256, 256>>>(Wm2, ec);
    biasmix_kernel<<<3, 256>>>(bm0, ec);

    gemm_fused<<<MAX_GT, 256, SMEM_BYTES>>>(out);
}

// round 8
// speedup vs baseline: 2.3806x; 1.0075x over previous
#include <cuda_runtime.h>
#include <cuda_fp16.h>
#include <cstdint>

// ---------------------------------------------------------------------------
// SO2ConvolutionMoE, FP16 mma.sync, fused GEMM + single fused preprocessing
// kernel (role-partitioned grid gives cvt/mix/bucket overlap WITHOUT extra
// streams -- multi-stream graphs leave pinned upload memory after teardown,
// which the harness rejects).
// ---------------------------------------------------------------------------

#define NEDGES 12288
#define NSYS   16
#define NEXP   8
#define ROWF   2432
#define MAX_GT (112 * 19)     // <= 2128 CTA tiles

__device__ __half g_B0[(size_t)NSYS * 640 * 640];     // [K][N]
__device__ __half g_B1[(size_t)NSYS * 1024 * 1024];
__device__ __half g_B2[(size_t)NSYS * 768 * 768];
__device__ float  g_bias0[NSYS * 640];
__device__ __half g_xh[(size_t)NEDGES * ROWF];
__device__ int    g_list[NSYS * NEDGES];
__device__ int    g_cnt[NSYS];
__device__ int    g_gdesc[MAX_GT];     // packed: seg(2) | sys(4) | nb(4) | m0(22)
__device__ int    g_ngt;

__device__ __forceinline__ uint32_t h2_as_u32(__half2 h) {
    return *reinterpret_cast<const uint32_t*>(&h);
}

// ---------------------------------------------------------------------------
__global__ void reset_kernel() {
    if (threadIdx.x < NSYS) g_cnt[threadIdx.x] = 0;
}

__global__ void plan_kernel() {
    if (threadIdx.x == 0) {
        const int segorder[3] = {1, 2, 0};     // longest K first
        const int nbs[3] = {5, 8, 6};          // n-blocks per seg (N/128)
        int ng = 0;
        for (int so = 0; so < 3; so++) {
            int seg = segorder[so];
            for (int s = 0; s < NSYS; s++) {
                int c = g_cnt[s];
                for (int m0 = 0; m0 < c; m0 += 128)
                    for (int nb = 0; nb < nbs[seg]; nb++)
                        g_gdesc[ng++] = (seg << 30) | (s << 26) | (nb << 22) | m0;
            }
        }
        g_ngt = ng;
    }
}

// ---------------------------------------------------------------------------
// Fused preprocessing: one kernel, blocks partitioned by role.
//   [0, NB_BKT)                       bucket (edge -> per-system lists)
//   [.., +NB_BIAS)                    bias mix
//   [.., +NB_M1), +NB_M2, +NB_M0      weight mixes (SO(2) recombined, fp16)
//   [.., +NB_CVT)                     x fp32 -> fp16
// ---------------------------------------------------------------------------
#define NB_BKT  48
#define NB_BIAS 3
#define NB_M1   1024     // (1024*1024/4)/256
#define NB_M2   576      // (768*768/4)/256
#define NB_M0   400      // (640*640/4)/256
#define NB_CVT  29184    // (12288*2432/4)/256
#define NB_PRE  (NB_BKT + NB_BIAS + NB_M1 + NB_M2 + NB_M0 + NB_CVT)

template <int MODE>
__device__ __forceinline__ void mix_body(const float* __restrict__ W,
                                         const float* __restrict__ ec, int bi) {
    constexpr int Kin   = (MODE == 0) ? 640 : (MODE == 1) ? 512 : 384;
    constexpr int Nw    = (MODE == 0) ? 640 : (MODE == 1) ? 1024 : 768;
    constexpr int SO2   = (MODE == 0) ? 0 : 1;
    constexpr int KTOT  = SO2 ? 2 * Kin : Kin;
    constexpr int TOTAL = KTOT * Nw;
    constexpr int N4    = Nw / 4;

    __half* Bd = (MODE == 0) ? g_B0 : (MODE == 1) ? g_B1 : g_B2;

    __shared__ float sec[NSYS * NEXP];
    if (threadIdx.x < NSYS * NEXP) sec[threadIdx.x] = ec[threadIdx.x];
    __syncthreads();

    int idx4 = bi * 256 + threadIdx.x;
    if (idx4 >= TOTAL / 4) return;
    int k  = idx4 / N4;
    int jj = idx4 - k * N4;

    float sign = 1.f;
    size_t src4;
    if (!SO2 || k < Kin) {
        src4 = (size_t)k * N4 + jj;
    } else {
        int kk = k - Kin;
        int Nh4 = N4 >> 1;
        if (jj < Nh4) { src4 = (size_t)kk * N4 + Nh4 + jj; sign = -1.f; }
        else          { src4 = (size_t)kk * N4 + (jj - Nh4); }
    }

    const size_t esz4 = (size_t)Kin * N4;
    float4 w[NEXP];
#pragma unroll
    for (int e = 0; e < NEXP; e++) w[e] = ((const float4*)W)[e * esz4 + src4];

#pragma unroll
    for (int s = 0; s < NSYS; s++) {
        float4 a = make_float4(0.f, 0.f, 0.f, 0.f);
#pragma unroll
        for (int e = 0; e < NEXP; e++) {
            float c = sec[s * NEXP + e];
            a.x = fmaf(c, w[e].x, a.x); a.y = fmaf(c, w[e].y, a.y);
            a.z = fmaf(c, w[e].z, a.z); a.w = fmaf(c, w[e].w, a.w);
        }
        uint2 u;
        u.x = h2_as_u32(__floats2half2_rn(sign * a.x, sign * a.y));
        u.y = h2_as_u32(__floats2half2_rn(sign * a.z, sign * a.w));
        *reinterpret_cast<uint2*>(Bd + (size_t)s * TOTAL + (size_t)idx4 * 4) = u;
    }
}

__global__ __launch_bounds__(256) void pre_fused(
    const float* __restrict__ x, const float* __restrict__ ec,
    const int* __restrict__ eb,
    const float* __restrict__ Wm0, const float* __restrict__ bm0,
    const float* __restrict__ Wm1, const float* __restrict__ Wm2) {
    int b = blockIdx.x;

    if (b < NB_BKT) {
        int i = b * 256 + threadIdx.x;
        if (i < NEDGES) {
            int s = eb[i];
            int p = atomicAdd(&g_cnt[s], 1);
            g_list[s * NEDGES + p] = i;
        }
        return;
    }
    b -= NB_BKT;

    if (b < NB_BIAS) {
        int j = b * 256 + threadIdx.x;
        if (j < 640) {
            float w[NEXP];
#pragma unroll
            for (int e = 0; e < NEXP; e++) w[e] = bm0[e * 640 + j];
#pragma unroll
            for (int s = 0; s < NSYS; s++) {
                float acc = 0.f;
#pragma unroll
                for (int e = 0; e < NEXP; e++)
                    acc = fmaf(ec[s * NEXP + e], w[e], acc);
                g_bias0[s * 640 + j] = acc;
            }
        }
        return;
    }
    b -= NB_BIAS;

    if (b < NB_M1) { mix_body<1>(Wm1, ec, b); return; }
    b -= NB_M1;
    if (b < NB_M2) { mix_body<2>(Wm2, ec, b); return; }
    b -= NB_M2;
    if (b < NB_M0) { mix_body<0>(Wm0, ec, b); return; }
    b -= NB_M0;

    // cvt: x fp32 -> fp16
    {
        int i = b * 256 + threadIdx.x;     // i < NB_CVT*256 == total4 exactly
        float4 v = ((const float4*)x)[i];
        uint2 u;
        u.x = h2_as_u32(__floats2half2_rn(v.x, v.y));
        u.y = h2_as_u32(__floats2half2_rn(v.z, v.w));
        *reinterpret_cast<uint2*>(g_xh + (size_t)i * 4) = u;
    }
}

// ---------------------------------------------------------------------------
// Fused FP16 grouped GEMM: 128x128 CTA tile, KTILE=64, 3-stage cp.async,
// 8 warps as 2M x 4N (warp tile 64x32), 2 CTAs/SM, 1 barrier / K-iter.
// ---------------------------------------------------------------------------
#define KTILE 64
#define SA_H 72              // 64 + 8 pad (halves)
#define SB_H 136             // 128 + 8 pad (halves)
#define STAGES 3
#define A_STAGE (128 * SA_H)
#define B_STAGE (KTILE * SB_H)
#define SMEM_HALVES (STAGES * (A_STAGE + B_STAGE))
#define SMEM_BYTES (SMEM_HALVES * 2 + 512)

__device__ __forceinline__ void mma_f16(float* d, const uint32_t* a, const uint32_t* b) {
    asm volatile(
        "mma.sync.aligned.m16n8k16.row.col.f32.f16.f16.f32 "
        "{%0,%1,%2,%3}, {%4,%5,%6,%7}, {%8,%9}, {%0,%1,%2,%3};\n"
        : "+f"(d[0]), "+f"(d[1]), "+f"(d[2]), "+f"(d[3])
        : "r"(a[0]), "r"(a[1]), "r"(a[2]), "r"(a[3]),
          "r"(b[0]), "r"(b[1]));
}

__device__ __forceinline__ void ldsm_x4(uint32_t* r, uint32_t saddr) {
    asm volatile("ldmatrix.sync.aligned.m8n8.x4.shared.b16 {%0,%1,%2,%3}, [%4];"
        : "=r"(r[0]), "=r"(r[1]), "=r"(r[2]), "=r"(r[3]) : "r"(saddr));
}

__device__ __forceinline__ void ldsm_x4_t(uint32_t* r, uint32_t saddr) {
    asm volatile("ldmatrix.sync.aligned.m8n8.x4.trans.shared.b16 {%0,%1,%2,%3}, [%4];"
        : "=r"(r[0]), "=r"(r[1]), "=r"(r[2]), "=r"(r[3]) : "r"(saddr));
}

__device__ __forceinline__ void cp16(void* dst, const void* src) {
    uint32_t sa = (uint32_t)__cvta_generic_to_shared(dst);
    asm volatile("cp.async.cg.shared.global [%0], [%1], 16;\n" :: "r"(sa), "l"(src));
}

__device__ __forceinline__ void cp16z(void* dst, const void* src, int sz) {
    uint32_t sa = (uint32_t)__cvta_generic_to_shared(dst);
    asm volatile("cp.async.cg.shared.global [%0], [%1], 16, %2;\n" :: "r"(sa), "l"(src), "r"(sz));
}

__global__ __launch_bounds__(256, 2) void gemm_fused(float* __restrict__ out) {
    const int ti = blockIdx.x;
    if (ti >= g_ngt) return;
    const int d   = g_gdesc[ti];
    const int seg = (d >> 30) & 3;
    const int sys = (d >> 26) & 15;
    const int n0  = ((d >> 22) & 15) * 128;
    const int m0  = d & 0x3FFFFF;
    const int cnt = g_cnt[sys];

    const int K    = (seg == 0) ? 640 : (seg == 1) ? 1024 : 768;
    const int XOFF = (seg == 0) ? 0 : (seg == 1) ? 640 : 1664;
    const int KT   = K / KTILE;
    const __half* Bsys =
        ((seg == 0) ? g_B0 : (seg == 1) ? g_B1 : g_B2) + (size_t)sys * K * K;

    extern __shared__ __half smh[];
    __half* sA = smh;                       // [STAGES][128][SA_H]
    __half* sB = smh + STAGES * A_STAGE;    // [STAGES][KTILE][SB_H]
    int*    sE = (int*)(smh + SMEM_HALVES); // [128]

    const int tid = threadIdx.x;

    if (tid < 128) {
        int idx = m0 + tid;
        sE[tid] = (idx < cnt) ? g_list[sys * NEDGES + idx] : -1;
    }
    __syncthreads();

    auto load_tile = [&](int kt, int buf) {
        __half* aBuf = sA + buf * A_STAGE;
        __half* bBuf = sB + buf * B_STAGE;
        // A: 128 rows x 64 halves = 1024 x 16B chunks
#pragma unroll
        for (int i = 0; i < 4; i++) {
            int c = tid + i * 256;
            int row = c >> 3, cc = c & 7;
            int e = sE[row];
            const __half* src = g_xh +
                ((e >= 0) ? ((size_t)e * ROWF + XOFF) : (size_t)0) + kt * KTILE + cc * 8;
            cp16z(aBuf + row * SA_H + cc * 8, src, (e >= 0) ? 16 : 0);
        }
        // B: 64 k-rows x 128 halves = 1024 x 16B chunks
#pragma unroll
        for (int i = 0; i < 4; i++) {
            int c = tid + i * 256;
            int k = c >> 4, n8 = c & 15;
            const __half* src = Bsys + (size_t)(kt * KTILE + k) * K + n0 + n8 * 8;
            cp16(bBuf + k * SB_H + n8 * 8, src);
        }
        asm volatile("cp.async.commit_group;\n" ::);
    };

    const int lane = tid & 31, warp = tid >> 5;
    const int wm = warp & 1, wn = warp >> 1;     // 2 M-warps x 4 N-warps
    const int gid = lane >> 2, tig = lane & 3;
    const int l15 = lane & 15, lhi = lane >> 4;

    float acc[4][4][4];
#pragma unroll
    for (int a = 0; a < 4; a++)
#pragma unroll
        for (int b = 0; b < 4; b++)
#pragma unroll
            for (int c = 0; c < 4; c++) acc[a][b][c] = 0.f;

    const uint32_t sA_u = (uint32_t)__cvta_generic_to_shared(sA);
    const uint32_t sB_u = (uint32_t)__cvta_generic_to_shared(sB);

    uint32_t aoff[4], boff[2];
#pragma unroll
    for (int mt = 0; mt < 4; mt++)
        aoff[mt] = ((wm * 64 + mt * 16 + l15) * SA_H + lhi * 8) * 2;
#pragma unroll
    for (int p = 0; p < 2; p++)
        boff[p] = (l15 * SB_H + wn * 32 + p * 16 + lhi * 8) * 2;

    // prologue: 2 stages in flight
    load_tile(0, 0);
    load_tile(1, 1);

    for (int kt = 0; kt < KT; kt++) {
        if (kt + 1 < KT) asm volatile("cp.async.wait_group 1;\n" ::);
        else             asm volatile("cp.async.wait_group 0;\n" ::);
        // One barrier per iter: also guarantees every thread finished reading
        // stage (kt-1) in the previous iteration, so load_tile into
        // (kt+2)%3 == (kt-1)%3 below is safe.
        __syncthreads();
        if (kt + 2 < KT) load_tile(kt + 2, (kt + 2) % STAGES);

        const int buf = kt % STAGES;
        const uint32_t aB = sA_u + buf * A_STAGE * 2;
        const uint32_t bB = sB_u + buf * B_STAGE * 2;

#pragma unroll
        for (int ks = 0; ks < 4; ks++) {
            uint32_t af[4][4], bf[4][2];
#pragma unroll
            for (int mt = 0; mt < 4; mt++)
                ldsm_x4(af[mt], aB + aoff[mt] + ks * 16 * 2);
#pragma unroll
            for (int p = 0; p < 2; p++) {
                uint32_t r[4];
                ldsm_x4_t(r, bB + boff[p] + ks * 16 * SB_H * 2);
                bf[2 * p][0] = r[0]; bf[2 * p][1] = r[1];
                bf[2 * p + 1][0] = r[2]; bf[2 * p + 1][1] = r[3];
            }
#pragma unroll
            for (int mt = 0; mt < 4; mt++)
#pragma unroll
                for (int nt = 0; nt < 4; nt++)
                    mma_f16(acc[mt][nt], af[mt], bf[nt]);
        }
    }

    // epilogue: scatter rows by edge id, fold bias for seg 0
#pragma unroll
    for (int mt = 0; mt < 4; mt++) {
        int r0 = wm * 64 + mt * 16 + gid;
        int e0 = sE[r0], e1 = sE[r0 + 8];
#pragma unroll
        for (int nt = 0; nt < 4; nt++) {
            int col = n0 + wn * 32 + nt * 8 + tig * 2;
            float b0 = 0.f, b1 = 0.f;
            if (seg == 0) {
                b0 = g_bias0[sys * 640 + col];
                b1 = g_bias0[sys * 640 + col + 1];
            }
            if (e0 >= 0) {
                float2 v;
                v.x = acc[mt][nt][0] + b0;
                v.y = acc[mt][nt][1] + b1;
                *(float2*)(out + (size_t)e0 * ROWF + XOFF + col) = v;
            }
            if (e1 >= 0) {
                float2 v;
                v.x = acc[mt][nt][2] + b0;
                v.y = acc[mt][nt][3] + b1;
                *(float2*)(out + (size_t)e1 * ROWF + XOFF + col) = v;
            }
        }
    }
}

// ---------------------------------------------------------------------------
extern "C" void kernel_launch(void* const* d_in, const int* in_sizes, int n_in,
                              void* d_out, int out_size) {
    const float* x   = (const float*)d_in[0];
    const float* ec  = (const float*)d_in[2];
    const int*   eb  = (const int*)d_in[3];
    const float* Wm0 = (const float*)d_in[4];
    const float* bm0 = (const float*)d_in[5];
    const float* Wm1 = (const float*)d_in[6];
    const float* Wm2 = (const float*)d_in[7];
    float* out = (float*)d_out;

    cudaFuncSetAttribute(gemm_fused, cudaFuncAttributeMaxDynamicSharedMemorySize,
                         SMEM_BYTES);

    reset_kernel<<<1, 32>>>();
    pre_fused<<<NB_PRE, 256>>>(x, ec, eb, Wm0, bm0, Wm1, Wm2);
    plan_kernel<<<1, 32>>>();
    gemm_fused<<<MAX_GT, 256, SMEM_BYTES>>>(out);
}

// round 9
// speedup vs baseline: 2.4463x; 1.0276x over previous
#include <cuda_runtime.h>
#include <cuda_fp16.h>
#include <cstdint>

// ---------------------------------------------------------------------------
// SO2ConvolutionMoE, FP16 mma.sync:
//   reset -> pre_fused (bucket + bias + 3 weight mixes + x->fp16, one grid)
//         -> gemm_fused (all 3 segments, tile descriptor derived per-CTA from
//            g_cnt -- no serial plan kernel).
// ---------------------------------------------------------------------------

#define NEDGES 12288
#define NSYS   16
#define NEXP   8
#define ROWF   2432
#define MAX_GT (112 * 19)     // upper bound on CTA tiles (19 = 8+6+5 nb per mtile)

__device__ __half g_B0[(size_t)NSYS * 640 * 640];     // [K][N]
__device__ __half g_B1[(size_t)NSYS * 1024 * 1024];
__device__ __half g_B2[(size_t)NSYS * 768 * 768];
__device__ float  g_bias0[NSYS * 640];
__device__ __half g_xh[(size_t)NEDGES * ROWF];
__device__ int    g_list[NSYS * NEDGES];
__device__ int    g_cnt[NSYS];

__device__ __forceinline__ uint32_t h2_as_u32(__half2 h) {
    return *reinterpret_cast<const uint32_t*>(&h);
}

// ---------------------------------------------------------------------------
__global__ void reset_kernel() {
    if (threadIdx.x < NSYS) g_cnt[threadIdx.x] = 0;
}

// ---------------------------------------------------------------------------
// Fused preprocessing: one kernel, blocks partitioned by role.
// ---------------------------------------------------------------------------
#define NB_BKT  48
#define NB_BIAS 3
#define NB_M1   1024     // (1024*1024/4)/256
#define NB_M2   576      // (768*768/4)/256
#define NB_M0   400      // (640*640/4)/256
#define NB_CVT  29184    // (12288*2432/4)/256
#define NB_PRE  (NB_BKT + NB_BIAS + NB_M1 + NB_M2 + NB_M0 + NB_CVT)

template <int MODE>
__device__ __forceinline__ void mix_body(const float* __restrict__ W,
                                         const float* __restrict__ ec, int bi) {
    constexpr int Kin   = (MODE == 0) ? 640 : (MODE == 1) ? 512 : 384;
    constexpr int Nw    = (MODE == 0) ? 640 : (MODE == 1) ? 1024 : 768;
    constexpr int SO2   = (MODE == 0) ? 0 : 1;
    constexpr int KTOT  = SO2 ? 2 * Kin : Kin;
    constexpr int TOTAL = KTOT * Nw;
    constexpr int N4    = Nw / 4;

    __half* Bd = (MODE == 0) ? g_B0 : (MODE == 1) ? g_B1 : g_B2;

    __shared__ float sec[NSYS * NEXP];
    if (threadIdx.x < NSYS * NEXP) sec[threadIdx.x] = ec[threadIdx.x];
    __syncthreads();

    int idx4 = bi * 256 + threadIdx.x;
    if (idx4 >= TOTAL / 4) return;
    int k  = idx4 / N4;
    int jj = idx4 - k * N4;

    float sign = 1.f;
    size_t src4;
    if (!SO2 || k < Kin) {
        src4 = (size_t)k * N4 + jj;
    } else {
        int kk = k - Kin;
        int Nh4 = N4 >> 1;
        if (jj < Nh4) { src4 = (size_t)kk * N4 + Nh4 + jj; sign = -1.f; }
        else          { src4 = (size_t)kk * N4 + (jj - Nh4); }
    }

    const size_t esz4 = (size_t)Kin * N4;
    float4 w[NEXP];
#pragma unroll
    for (int e = 0; e < NEXP; e++) w[e] = ((const float4*)W)[e * esz4 + src4];

#pragma unroll
    for (int s = 0; s < NSYS; s++) {
        float4 a = make_float4(0.f, 0.f, 0.f, 0.f);
#pragma unroll
        for (int e = 0; e < NEXP; e++) {
            float c = sec[s * NEXP + e];
            a.x = fmaf(c, w[e].x, a.x); a.y = fmaf(c, w[e].y, a.y);
            a.z = fmaf(c, w[e].z, a.z); a.w = fmaf(c, w[e].w, a.w);
        }
        uint2 u;
        u.x = h2_as_u32(__floats2half2_rn(sign * a.x, sign * a.y));
        u.y = h2_as_u32(__floats2half2_rn(sign * a.z, sign * a.w));
        *reinterpret_cast<uint2*>(Bd + (size_t)s * TOTAL + (size_t)idx4 * 4) = u;
    }
}

__global__ __launch_bounds__(256) void pre_fused(
    const float* __restrict__ x, const float* __restrict__ ec,
    const int* __restrict__ eb,
    const float* __restrict__ Wm0, const float* __restrict__ bm0,
    const float* __restrict__ Wm1, const float* __restrict__ Wm2) {
    int b = blockIdx.x;

    if (b < NB_BKT) {
        int i = b * 256 + threadIdx.x;
        if (i < NEDGES) {
            int s = eb[i];
            int p = atomicAdd(&g_cnt[s], 1);
            g_list[s * NEDGES + p] = i;
        }
        return;
    }
    b -= NB_BKT;

    if (b < NB_BIAS) {
        int j = b * 256 + threadIdx.x;
        if (j < 640) {
            float w[NEXP];
#pragma unroll
            for (int e = 0; e < NEXP; e++) w[e] = bm0[e * 640 + j];
#pragma unroll
            for (int s = 0; s < NSYS; s++) {
                float acc = 0.f;
#pragma unroll
                for (int e = 0; e < NEXP; e++)
                    acc = fmaf(ec[s * NEXP + e], w[e], acc);
                g_bias0[s * 640 + j] = acc;
            }
        }
        return;
    }
    b -= NB_BIAS;

    if (b < NB_M1) { mix_body<1>(Wm1, ec, b); return; }
    b -= NB_M1;
    if (b < NB_M2) { mix_body<2>(Wm2, ec, b); return; }
    b -= NB_M2;
    if (b < NB_M0) { mix_body<0>(Wm0, ec, b); return; }
    b -= NB_M0;

    // cvt: x fp32 -> fp16
    {
        int i = b * 256 + threadIdx.x;     // i < NB_CVT*256 == total4 exactly
        float4 v = ((const float4*)x)[i];
        uint2 u;
        u.x = h2_as_u32(__floats2half2_rn(v.x, v.y));
        u.y = h2_as_u32(__floats2half2_rn(v.z, v.w));
        *reinterpret_cast<uint2*>(g_xh + (size_t)i * 4) = u;
    }
}

// ---------------------------------------------------------------------------
// Fused FP16 grouped GEMM: 128x128 CTA tile, KTILE=64, 3-stage cp.async,
// 8 warps as 2M x 4N (warp tile 64x32), 2 CTAs/SM, 1 barrier / K-iter.
// Tile descriptor computed per-CTA from g_cnt (no plan kernel).
// ---------------------------------------------------------------------------
#define KTILE 64
#define SA_H 72              // 64 + 8 pad (halves)
#define SB_H 136             // 128 + 8 pad (halves)
#define STAGES 3
#define A_STAGE (128 * SA_H)
#define B_STAGE (KTILE * SB_H)
#define SMEM_HALVES (STAGES * (A_STAGE + B_STAGE))
#define SMEM_BYTES (SMEM_HALVES * 2 + 512)

__device__ __forceinline__ void mma_f16(float* d, const uint32_t* a, const uint32_t* b) {
    asm volatile(
        "mma.sync.aligned.m16n8k16.row.col.f32.f16.f16.f32 "
        "{%0,%1,%2,%3}, {%4,%5,%6,%7}, {%8,%9}, {%0,%1,%2,%3};\n"
        : "+f"(d[0]), "+f"(d[1]), "+f"(d[2]), "+f"(d[3])
        : "r"(a[0]), "r"(a[1]), "r"(a[2]), "r"(a[3]),
          "r"(b[0]), "r"(b[1]));
}

__device__ __forceinline__ void ldsm_x4(uint32_t* r, uint32_t saddr) {
    asm volatile("ldmatrix.sync.aligned.m8n8.x4.shared.b16 {%0,%1,%2,%3}, [%4];"
        : "=r"(r[0]), "=r"(r[1]), "=r"(r[2]), "=r"(r[3]) : "r"(saddr));
}

__device__ __forceinline__ void ldsm_x4_t(uint32_t* r, uint32_t saddr) {
    asm volatile("ldmatrix.sync.aligned.m8n8.x4.trans.shared.b16 {%0,%1,%2,%3}, [%4];"
        : "=r"(r[0]), "=r"(r[1]), "=r"(r[2]), "=r"(r[3]) : "r"(saddr));
}

__device__ __forceinline__ void cp16(void* dst, const void* src) {
    uint32_t sa = (uint32_t)__cvta_generic_to_shared(dst);
    asm volatile("cp.async.cg.shared.global [%0], [%1], 16;\n" :: "r"(sa), "l"(src));
}

__device__ __forceinline__ void cp16z(void* dst, const void* src, int sz) {
    uint32_t sa = (uint32_t)__cvta_generic_to_shared(dst);
    asm volatile("cp.async.cg.shared.global [%0], [%1], 16, %2;\n" :: "r"(sa), "l"(src), "r"(sz));
}

__global__ __launch_bounds__(256, 2) void gemm_fused(float* __restrict__ out) {
    const int tid = threadIdx.x;

    // --- derive (seg, sys, m0, nb) from blockIdx.x using g_cnt only ---
    __shared__ int scnt[NSYS];
    if (tid < NSYS) scnt[tid] = g_cnt[tid];
    __syncthreads();

    int ms[NSYS];
    int total = 0;
#pragma unroll
    for (int s = 0; s < NSYS; s++) { ms[s] = (scnt[s] + 127) >> 7; total += ms[s]; }

    // tile order: seg1 (nbs=8), seg2 (nbs=6), seg0 (nbs=5); within a segment
    // m-tiles outer, n-blocks inner.
    int t = blockIdx.x;
    int seg, nbs_;
    if (t < 8 * total) { seg = 1; nbs_ = 8; }
    else {
        t -= 8 * total;
        if (t < 6 * total) { seg = 2; nbs_ = 6; }
        else {
            t -= 6 * total;
            if (t < 5 * total) { seg = 0; nbs_ = 5; }
            else return;
        }
    }
    int mt = t / nbs_;
    const int n0 = (t - mt * nbs_) * 128;
    int sys = 0;
    while (mt >= ms[sys]) { mt -= ms[sys]; sys++; }
    const int m0  = mt << 7;
    const int cnt = scnt[sys];

    const int K    = (seg == 0) ? 640 : (seg == 1) ? 1024 : 768;
    const int XOFF = (seg == 0) ? 0 : (seg == 1) ? 640 : 1664;
    const int KT   = K / KTILE;
    const __half* Bsys =
        ((seg == 0) ? g_B0 : (seg == 1) ? g_B1 : g_B2) + (size_t)sys * K * K;

    extern __shared__ __half smh[];
    __half* sA = smh;                       // [STAGES][128][SA_H]
    __half* sB = smh + STAGES * A_STAGE;    // [STAGES][KTILE][SB_H]
    int*    sE = (int*)(smh + SMEM_HALVES); // [128]

    if (tid < 128) {
        int idx = m0 + tid;
        sE[tid] = (idx < cnt) ? g_list[sys * NEDGES + idx] : -1;
    }
    __syncthreads();

    auto load_tile = [&](int kt, int buf) {
        __half* aBuf = sA + buf * A_STAGE;
        __half* bBuf = sB + buf * B_STAGE;
        // A: 128 rows x 64 halves = 1024 x 16B chunks
#pragma unroll
        for (int i = 0; i < 4; i++) {
            int c = tid + i * 256;
            int row = c >> 3, cc = c & 7;
            int e = sE[row];
            const __half* src = g_xh +
                ((e >= 0) ? ((size_t)e * ROWF + XOFF) : (size_t)0) + kt * KTILE + cc * 8;
            cp16z(aBuf + row * SA_H + cc * 8, src, (e >= 0) ? 16 : 0);
        }
        // B: 64 k-rows x 128 halves = 1024 x 16B chunks
#pragma unroll
        for (int i = 0; i < 4; i++) {
            int c = tid + i * 256;
            int k = c >> 4, n8 = c & 15;
            const __half* src = Bsys + (size_t)(kt * KTILE + k) * K + n0 + n8 * 8;
            cp16(bBuf + k * SB_H + n8 * 8, src);
        }
        asm volatile("cp.async.commit_group;\n" ::);
    };

    const int lane = tid & 31, warp = tid >> 5;
    const int wm = warp & 1, wn = warp >> 1;     // 2 M-warps x 4 N-warps
    const int gid = lane >> 2, tig = lane & 3;
    const int l15 = lane & 15, lhi = lane >> 4;

    float acc[4][4][4];
#pragma unroll
    for (int a = 0; a < 4; a++)
#pragma unroll
        for (int b = 0; b < 4; b++)
#pragma unroll
            for (int c = 0; c < 4; c++) acc[a][b][c] = 0.f;

    const uint32_t sA_u = (uint32_t)__cvta_generic_to_shared(sA);
    const uint32_t sB_u = (uint32_t)__cvta_generic_to_shared(sB);

    uint32_t aoff[4], boff[2];
#pragma unroll
    for (int mt2 = 0; mt2 < 4; mt2++)
        aoff[mt2] = ((wm * 64 + mt2 * 16 + l15) * SA_H + lhi * 8) * 2;
#pragma unroll
    for (int p = 0; p < 2; p++)
        boff[p] = (l15 * SB_H + wn * 32 + p * 16 + lhi * 8) * 2;

    // prologue: 2 stages in flight
    load_tile(0, 0);
    load_tile(1, 1);

    for (int kt = 0; kt < KT; kt++) {
        if (kt + 1 < KT) asm volatile("cp.async.wait_group 1;\n" ::);
        else             asm volatile("cp.async.wait_group 0;\n" ::);
        // One barrier per iter: also guarantees every thread finished reading
        // stage (kt-1) in the previous iteration, so load_tile into
        // (kt+2)%3 == (kt-1)%3 below is safe.
        __syncthreads();
        if (kt + 2 < KT) load_tile(kt + 2, (kt + 2) % STAGES);

        const int buf = kt % STAGES;
        const uint32_t aB = sA_u + buf * A_STAGE * 2;
        const uint32_t bB = sB_u + buf * B_STAGE * 2;

#pragma unroll
        for (int ks = 0; ks < 4; ks++) {
            uint32_t af[4][4], bf[4][2];
#pragma unroll
            for (int mt2 = 0; mt2 < 4; mt2++)
                ldsm_x4(af[mt2], aB + aoff[mt2] + ks * 16 * 2);
#pragma unroll
            for (int p = 0; p < 2; p++) {
                uint32_t r[4];
                ldsm_x4_t(r, bB + boff[p] + ks * 16 * SB_H * 2);
                bf[2 * p][0] = r[0]; bf[2 * p][1] = r[1];
                bf[2 * p + 1][0] = r[2]; bf[2 * p + 1][1] = r[3];
            }
#pragma unroll
            for (int mt2 = 0; mt2 < 4; mt2++)
#pragma unroll
                for (int nt = 0; nt < 4; nt++)
                    mma_f16(acc[mt2][nt], af[mt2], bf[nt]);
        }
    }

    // epilogue: scatter rows by edge id, fold bias for seg 0
#pragma unroll
    for (int mt2 = 0; mt2 < 4; mt2++) {
        int r0 = wm * 64 + mt2 * 16 + gid;
        int e0 = sE[r0], e1 = sE[r0 + 8];
#pragma unroll
        for (int nt = 0; nt < 4; nt++) {
            int col = n0 + wn * 32 + nt * 8 + tig * 2;
            float b0 = 0.f, b1 = 0.f;
            if (seg == 0) {
                b0 = g_bias0[sys * 640 + col];
                b1 = g_bias0[sys * 640 + col + 1];
            }
            if (e0 >= 0) {
                float2 v;
                v.x = acc[mt2][nt][0] + b0;
                v.y = acc[mt2][nt][1] + b1;
                *(float2*)(out + (size_t)e0 * ROWF + XOFF + col) = v;
            }
            if (e1 >= 0) {
                float2 v;
                v.x = acc[mt2][nt][2] + b0;
                v.y = acc[mt2][nt][3] + b1;
                *(float2*)(out + (size_t)e1 * ROWF + XOFF + col) = v;
            }
        }
    }
}

// ---------------------------------------------------------------------------
extern "C" void kernel_launch(void* const* d_in, const int* in_sizes, int n_in,
                              void* d_out, int out_size) {
    const float* x   = (const float*)d_in[0];
    const float* ec  = (const float*)d_in[2];
    const int*   eb  = (const int*)d_in[3];
    const float* Wm0 = (const float*)d_in[4];
    const float* bm0 = (const float*)d_in[5];
    const float* Wm1 = (const float*)d_in[6];
    const float* Wm2 = (const float*)d_in[7];
    float* out = (float*)d_out;

    cudaFuncSetAttribute(gemm_fused, cudaFuncAttributeMaxDynamicSharedMemorySize,
                         SMEM_BYTES);

    reset_kernel<<<1, 32>>>();
    pre_fused<<<NB_PRE, 256>>>(x, ec, eb, Wm0, bm0, Wm1, Wm2);
    gemm_fused<<<MAX_GT, 256, SMEM_BYTES>>>(out);
}